// round 5
// baseline (speedup 1.0000x reference)
#include <cuda_runtime.h>
#include <cstdint>

// Problem constants (fixed by the dataset)
#define BB   8192      // batch rows
#define DIN  1024
#define NC   256       // padded gating columns (120 z + 128 a + 8 pad)
#define NE   16
#define KK8  8

// ---------------- scratch (no allocation allowed) ----------------
__device__ float g_Wt [DIN * NC];    // packed+padded gating weights [d][c]
__device__ float g_mid[BB  * NC];    // pre-bias gating GEMM result [b][c]
__device__ float g_w  [BB  * NE];    // final expert weights [b][n]

typedef unsigned long long ull;

__device__ __forceinline__ ull ffma2(ull a, ull b, ull c) {
    ull d;
    asm("fma.rn.f32x2 %0, %1, %2, %3;" : "=l"(d) : "l"(a), "l"(b), "l"(c));
    return d;
}

#define CPA16(dst, src) \
    asm volatile("cp.async.ca.shared.global [%0], [%1], 16;\n" :: "r"(dst), "l"(src))

// ---------------- kernel 0: pack Wz (15,1024,8) and Ww (16,1024,8) into [1024][256] ----------------
__global__ void prepack_kernel(const float* __restrict__ Wz, const float* __restrict__ Ww) {
    int d = blockIdx.x;
    int c = threadIdx.x;
    float v = 0.0f;
    if (c < 120) {
        v = Wz[(c >> 3) * (DIN * 8) + d * 8 + (c & 7)];
    } else if (c < 248) {
        int cc = c - 120;
        v = Ww[(cc >> 3) * (DIN * 8) + d * 8 + (cc & 7)];
    }
    g_Wt[d * NC + c] = v;
}

// ---------------- kernel 1: gating GEMM  mid[b][c] = sum_d x[b][d] * Wt[d][c] ----------------
// Tile: 64 rows x 256 cols, BK=16. 256 threads; thread (ty,tx) -> 8 rows x 8 cols micro-tile,
// accumulated as 8x4 packed f32x2. A staged duplicated (a,a) in smem; B via cp.async, 2 stages.
__global__ __launch_bounds__(256, 1) void gemm_kernel(const float* __restrict__ x) {
    extern __shared__ char sm[];
    float2* sA = (float2*)sm;                  // [2][16][64] duplicated A
    float*  sB = (float*)(sm + 16384);         // [2][16][256]
    const uint32_t sB_u32 = (uint32_t)__cvta_generic_to_shared(sB);

    const int tid  = threadIdx.x;
    const int ty   = tid >> 5;     // 0..7  (row group)
    const int tx   = tid & 31;     // 0..31 (col group)
    const int r0   = blockIdx.x * 64;
    const int arow = tid >> 2;     // 0..63
    const int akq  = tid & 3;      // 0..3

    const float* gA = x + (size_t)(r0 + arow) * DIN + akq * 4;
    const float* gB = g_Wt + tid * 16;
    const uint32_t sBoff = sB_u32 + tid * 64;  // byte offset inside a stage

    ull acc[8][4];
#pragma unroll
    for (int i = 0; i < 8; i++)
#pragma unroll
        for (int p = 0; p < 4; p++) acc[i][p] = 0ull;

    // ---- prologue: stage 0 ----
    float4 areg = *(const float4*)(gA);
    {
        const char* g = (const char*)gB;
        CPA16(sBoff +  0, g +  0);
        CPA16(sBoff + 16, g + 16);
        CPA16(sBoff + 32, g + 32);
        CPA16(sBoff + 48, g + 48);
        asm volatile("cp.async.commit_group;\n");
    }
    {
        float2* p = sA + (akq * 4) * 64 + arow;
        p[0 * 64] = make_float2(areg.x, areg.x);
        p[1 * 64] = make_float2(areg.y, areg.y);
        p[2 * 64] = make_float2(areg.z, areg.z);
        p[3 * 64] = make_float2(areg.w, areg.w);
    }
    asm volatile("cp.async.wait_group 0;\n");
    __syncthreads();

    for (int ct = 0; ct < 64; ++ct) {
        const int cur = ct & 1;
        float4 anext;
        if (ct < 63) {
            anext = *(const float4*)(gA + (ct + 1) * 16);
            const char* g = (const char*)(gB + (ct + 1) * 4096);
            uint32_t s = sBoff + (cur ^ 1) * 16384;
            CPA16(s +  0, g +  0);
            CPA16(s + 16, g + 16);
            CPA16(s + 32, g + 32);
            CPA16(s + 48, g + 48);
            asm volatile("cp.async.commit_group;\n");
        }

        const float2* pa0 = sA + cur * 1024 + ty * 8;
        const float*  pb0 = sB + cur * 4096 + tx * 8;
#pragma unroll
        for (int kkk = 0; kkk < 16; ++kkk) {
            const ull* pa = (const ull*)(pa0 + kkk * 64);
            const ulonglong2* pb = (const ulonglong2*)(pb0 + kkk * 256);
            ulonglong2 q0 = pb[0];
            ulonglong2 q1 = pb[1];
#pragma unroll
            for (int i = 0; i < 8; i++) {
                ull a = pa[i];
                acc[i][0] = ffma2(a, q0.x, acc[i][0]);
                acc[i][1] = ffma2(a, q0.y, acc[i][1]);
                acc[i][2] = ffma2(a, q1.x, acc[i][2]);
                acc[i][3] = ffma2(a, q1.y, acc[i][3]);
            }
        }

        if (ct < 63) {
            float2* p = sA + (cur ^ 1) * 1024 + (akq * 4) * 64 + arow;
            p[0 * 64] = make_float2(anext.x, anext.x);
            p[1 * 64] = make_float2(anext.y, anext.y);
            p[2 * 64] = make_float2(anext.z, anext.z);
            p[3 * 64] = make_float2(anext.w, anext.w);
            asm volatile("cp.async.wait_group 0;\n");
        }
        __syncthreads();
    }

    // write results (pre-bias) to global
#pragma unroll
    for (int i = 0; i < 8; i++) {
        float* dst = g_mid + (size_t)(r0 + ty * 8 + i) * NC + tx * 8;
#pragma unroll
        for (int p = 0; p < 4; p++) {
            *(float2*)(dst + 2 * p) = *(float2*)&acc[i][p];
        }
    }
}

// ---------------- kernel 2: per-row epilogue -> expert weights w[b][16] ----------------
__device__ __forceinline__ float smoothstep_f(float v) {
    // gamma = 1: v<=-0.5 -> 0 ; v>=0.5 -> 1 ; else -2v^3 + 1.5v + 0.5
    if (v <= -0.5f) return 0.0f;
    if (v >=  0.5f) return 1.0f;
    return fmaf(-2.0f * v * v, v, fmaf(1.5f, v, 0.5f));
}

__global__ __launch_bounds__(256) void epi_kernel(const float* __restrict__ bz,
                                                  const float* __restrict__ bw,
                                                  const float* __restrict__ P) {
    const int warp = threadIdx.x >> 5;
    const int lane = threadIdx.x & 31;
    const int row  = blockIdx.x * 8 + warp;

    __shared__ float ss[8][120];

    const float* Rm = g_mid + (size_t)row * NC;

    for (int c = lane; c < 120; c += 32)
        ss[warp][c] = smoothstep_f(Rm[c] + bz[c]);
    __syncwarp();

    float L[4];
    int   q[4];
    float m = -3.4028234663852886e38f;
#pragma unroll
    for (int t = 0; t < 4; t++) {
        int qq = lane + 32 * t;
        q[t] = qq;
        int n = qq >> 3, k = qq & 7;
        float p = 1.0f;
#pragma unroll
        for (int l = 0; l < 4; l++) {
            int node = (1 << l) - 1 + (n >> (4 - l));
            int bit  = (n >> (3 - l)) & 1;
            float sv = ss[warp][node * 8 + k];
            p *= bit ? (1.0f - sv) : sv;
        }
        float lp = (p <= 0.0f) ? -3.4028234663852886e38f : __logf(p + 1e-8f);
        L[t] = Rm[120 + qq] + bw[qq] + lp;
        m = fmaxf(m, L[t]);
    }
#pragma unroll
    for (int off = 16; off; off >>= 1)
        m = fmaxf(m, __shfl_xor_sync(0xffffffffu, m, off));

    float wt[16];
#pragma unroll
    for (int l = 0; l < 16; l++) wt[l] = 0.0f;

#pragma unroll
    for (int t = 0; t < 4; t++) {
        float e = __expf(L[t] - m);   // softmax 1/sum cancels in final normalization
        int n = q[t] >> 3, k = q[t] & 7;
        const float4* Pp = (const float4*)(P + ((size_t)(k * 16 + n)) * 16);
#pragma unroll
        for (int u = 0; u < 4; u++) {
            float4 pv = Pp[u];
            wt[4 * u + 0] = fmaf(e, pv.x, wt[4 * u + 0]);
            wt[4 * u + 1] = fmaf(e, pv.y, wt[4 * u + 1]);
            wt[4 * u + 2] = fmaf(e, pv.z, wt[4 * u + 2]);
            wt[4 * u + 3] = fmaf(e, pv.w, wt[4 * u + 3]);
        }
    }
#pragma unroll
    for (int off = 16; off; off >>= 1)
#pragma unroll
        for (int l = 0; l < 16; l++)
            wt[l] += __shfl_xor_sync(0xffffffffu, wt[l], off);

    float tot = 0.0f;
#pragma unroll
    for (int l = 0; l < 16; l++) tot += wt[l];

    if (lane < 16)
        g_w[(size_t)row * 16 + lane] = wt[lane] / tot;
}

// ---------------- kernel 3: y[b][d] = sum_n f[b][d][n] * w[b][n] (DRAM-bound) ----------------
__global__ __launch_bounds__(256) void y_kernel(const float* __restrict__ f,
                                                float* __restrict__ y) {
    const int b = blockIdx.x;
    __shared__ float sw[16];
    if (threadIdx.x < 16) sw[threadIdx.x] = g_w[b * 16 + threadIdx.x];
    __syncthreads();

    float w[16];
#pragma unroll
    for (int n = 0; n < 16; n++) w[n] = sw[n];

    const float4* fb = (const float4*)(f + (size_t)b * 16384);
    float* yb = y + (size_t)b * 1024;

#pragma unroll
    for (int t = 0; t < 4; t++) {
        int d = threadIdx.x + t * 256;
        float4 v0 = fb[d * 4 + 0];
        float4 v1 = fb[d * 4 + 1];
        float4 v2 = fb[d * 4 + 2];
        float4 v3 = fb[d * 4 + 3];
        float acc;
        acc = v0.x * w[0];
        acc = fmaf(v0.y, w[1],  acc);
        acc = fmaf(v0.z, w[2],  acc);
        acc = fmaf(v0.w, w[3],  acc);
        acc = fmaf(v1.x, w[4],  acc);
        acc = fmaf(v1.y, w[5],  acc);
        acc = fmaf(v1.z, w[6],  acc);
        acc = fmaf(v1.w, w[7],  acc);
        acc = fmaf(v2.x, w[8],  acc);
        acc = fmaf(v2.y, w[9],  acc);
        acc = fmaf(v2.z, w[10], acc);
        acc = fmaf(v2.w, w[11], acc);
        acc = fmaf(v3.x, w[12], acc);
        acc = fmaf(v3.y, w[13], acc);
        acc = fmaf(v3.z, w[14], acc);
        acc = fmaf(v3.w, w[15], acc);
        yb[d] = acc;
    }
}

// ---------------- launcher ----------------
extern "C" void kernel_launch(void* const* d_in, const int* in_sizes, int n_in,
                              void* d_out, int out_size) {
    const float* f  = (const float*)d_in[0];  // (B, 1024, 16)
    const float* x  = (const float*)d_in[1];  // (B, 1024)
    const float* P  = (const float*)d_in[2];  // (8, 16, 16)
    const float* Wz = (const float*)d_in[3];  // (15, 1024, 8)
    const float* bz = (const float*)d_in[4];  // (15, 8)
    const float* Ww = (const float*)d_in[5];  // (16, 1024, 8)
    const float* bw = (const float*)d_in[6];  // (16, 8)
    float* y = (float*)d_out;                 // (B, 1024)

    prepack_kernel<<<DIN, 256>>>(Wz, Ww);
    gemm_kernel<<<BB / 64, 256, 49152>>>(x);
    epi_kernel<<<BB / 8, 256>>>(bz, bw, P);
    y_kernel<<<BB, 256>>>(f, y);
}